// round 10
// baseline (speedup 1.0000x reference)
#include <cuda_runtime.h>

// Shapes (fixed): B=2, N=512, M=512, Dq=Dk=Dv=128, De=64, H=8, O=32, OUT=128

#define BB 2
#define NN 512
#define MM 512
#define HH 8
#define OO 32
#define DE 64

typedef unsigned long long u64;

// Scratch (no cudaMalloc allowed). ~4.5 MB total.
__device__ __align__(256) float g_qh[BB*NN*HH*OO];   // [row][h*32+o]   (q/sqrt(32) @ Wq)
__device__ __align__(256) float g_qe[BB*NN*HH*DE];   // [row][h*64+j]   (qh @ Wk_edge^T)
__device__ __align__(256) float g_kk[BB*MM*OO*HH];   // [row][o*8+h]    h-pair packed
__device__ __align__(256) float g_vT[BB*512*256];    // [b][m/4][c][4]  m-pair packed, c=h*32+o

// ---------------------------------------------------------------------------
// Packed fp32x2 helpers (Blackwell FFMA2 — via PTX fma.rn.f32x2)
// ---------------------------------------------------------------------------
__device__ __forceinline__ void fma2(u64 &d, u64 a, u64 b) {
    asm("fma.rn.f32x2 %0, %1, %2, %0;" : "+l"(d) : "l"(a), "l"(b));
}
__device__ __forceinline__ u64 bcast2(float x) {
    u64 r; asm("mov.b64 %0, {%1, %1};" : "=l"(r) : "f"(x)); return r;
}
__device__ __forceinline__ float2 unpack2(u64 v) {
    float2 f; asm("mov.b64 {%0, %1}, %2;" : "=f"(f.x), "=f"(f.y) : "l"(v)); return f;
}

// ---------------------------------------------------------------------------
// Fused prologue: 512 blocks x 256 threads.
//   block id: type = id&1 (0: q-side, 1: kv-side), h = (id>>1)&7, chunk = id>>4
//   Each block: 32 rows, weights for ONE head staged in smem.
// ---------------------------------------------------------------------------
__global__ __launch_bounds__(256) void prologue_kernel(
    const float* __restrict__ query,
    const float* __restrict__ key,
    const float* __restrict__ value,
    const float* __restrict__ Wq,   // [H,128,32]
    const float* __restrict__ Wk,   // [H,192,32]
    const float* __restrict__ Wv)   // [H,128,32]
{
    __shared__ float sm[16384];
    const int tid = threadIdx.x;
    const int id = blockIdx.x;
    const int type = id & 1;
    const int h = (id >> 1) & 7;
    const int chunk = id >> 4;      // 0..31
    const int r0 = chunk * 32;      // global row base (0..1023)

    if (type == 0) {
        float* q_s  = sm;           // [32][128]
        float* Wq_s = sm + 4096;    // [128][32]
        float* We_s = sm + 8192;    // [o][j] = [32][64]
        float* qh_s = sm + 10240;   // [32][32]

        for (int i = tid; i < 4096; i += 256) {
            q_s[i]  = query[r0 * 128 + i];
            Wq_s[i] = Wq[h * 4096 + i];
        }
        for (int i = tid; i < 2048; i += 256) {
            int j = i >> 5, o = i & 31;
            We_s[o * 64 + j] = Wk[h * 6144 + 4096 + i];   // Wk[h][128+j][o]
        }
        __syncthreads();

        // qh = q @ Wq_h, scaled
        {
            const int o = tid & 31, rg = tid >> 5;        // rows rg*4 .. rg*4+3
            float acc[4] = {0.f, 0.f, 0.f, 0.f};
#pragma unroll 4
            for (int i = 0; i < 128; i++) {
                float w = Wq_s[i * 32 + o];
#pragma unroll
                for (int c = 0; c < 4; c++) acc[c] += q_s[(rg * 4 + c) * 128 + i] * w;
            }
            const float scale = 0.17677669529663687f;     // 1/sqrt(32)
#pragma unroll
            for (int c = 0; c < 4; c++) {
                int r = rg * 4 + c;
                float v = acc[c] * scale;
                qh_s[r * 32 + o] = v;
                g_qh[(r0 + r) * 256 + h * 32 + o] = v;
            }
        }
        __syncthreads();

        // qe[h][j] = sum_o qh[h][o] * We[j][o]
        {
            const int j = tid & 63, rg = tid >> 6;        // rows rg*8 .. rg*8+7
            float acc[8] = {0.f,0.f,0.f,0.f,0.f,0.f,0.f,0.f};
#pragma unroll 4
            for (int o = 0; o < 32; o++) {
                float w = We_s[o * 64 + j];
#pragma unroll
                for (int c = 0; c < 8; c++) acc[c] += qh_s[(rg * 8 + c) * 32 + o] * w;
            }
#pragma unroll
            for (int c = 0; c < 8; c++)
                g_qe[(r0 + rg * 8 + c) * 512 + h * 64 + j] = acc[c];
        }
    } else {
        float* k_s  = sm;
        float* v_s  = sm + 4096;
        float* Wk_s = sm + 8192;
        float* Wv_s = sm + 12288;

        for (int i = tid; i < 4096; i += 256) {
            k_s[i]  = key[r0 * 128 + i];
            v_s[i]  = value[r0 * 128 + i];
            Wk_s[i] = Wk[h * 6144 + i];      // key part of Wk[h]
            Wv_s[i] = Wv[h * 4096 + i];
        }
        __syncthreads();

        const int o = tid & 31, rg = tid >> 5;
        float ak[4] = {0.f,0.f,0.f,0.f}, av[4] = {0.f,0.f,0.f,0.f};
#pragma unroll 4
        for (int i = 0; i < 128; i++) {
            float wk = Wk_s[i * 32 + o];
            float wv = Wv_s[i * 32 + o];
#pragma unroll
            for (int c = 0; c < 4; c++) {
                ak[c] += k_s[(rg * 4 + c) * 128 + i] * wk;
                av[c] += v_s[(rg * 4 + c) * 128 + i] * wv;
            }
        }
#pragma unroll
        for (int c = 0; c < 4; c++) {
            int r = r0 + rg * 4 + c;
            g_kk[(r * 32 + o) * 8 + h] = ak[c];   // h-pair packed layout
        }

        // transpose av through smem (padded) then write g_vT coalesced
        __syncthreads();                 // everyone done reading k_s region
        float* vt = sm;                  // [32 o][33] padded
#pragma unroll
        for (int c = 0; c < 4; c++)
            vt[o * 33 + rg * 4 + c] = av[c];
        __syncthreads();

        {
            const int o2 = tid >> 3, r4 = tid & 7;    // each thread: 4 m's for channel (h,o2)
            float4 val;
            val.x = vt[o2 * 33 + r4 * 4 + 0];
            val.y = vt[o2 * 33 + r4 * 4 + 1];
            val.z = vt[o2 * 33 + r4 * 4 + 2];
            val.w = vt[o2 * 33 + r4 * 4 + 3];
            const int b = r0 >> 9, mm0 = r0 & 511;
            size_t fidx = ((size_t)(b * 128 + (mm0 >> 2) + r4) * 256 + (h * 32 + o2)) * 4;
            *(float4*)&g_vT[fidx] = val;
        }
    }
}

// ---------------------------------------------------------------------------
// Main fused kernel: block = (b, 4 n-rows). 256 threads.
// Dynamic smem: 20512 floats = 82048 bytes.
//   Ls   [32][512]  logits/probs  (row = n*8+h)     @0
//   qhp  [n][o][h]                                  @16384
//   qep  [n][j][h]                                  @17408
//   mh_s [4][256]                                   @19456
//   rsum [32]                                       @20480
// ---------------------------------------------------------------------------
#define SMEM_BYTES (20512 * 4)

__global__ __launch_bounds__(256, 2) void attn_kernel(
    const float* __restrict__ edge,   // [B,N,M,64]
    const float* __restrict__ P,      // [H,32,128]
    const float* __restrict__ bias,   // [128]
    float* __restrict__ out)          // [B,N,128]
{
    extern __shared__ float smem[];
    float* Ls   = smem;            // 16384
    float* qhp  = smem + 16384;    // 1024
    float* qep  = smem + 17408;    // 2048
    float* mh_s = smem + 19456;    // 1024
    float* rsum = smem + 20480;    // 32

    const int tid = threadIdx.x;
    const int b  = blockIdx.x >> 7;
    const int n0 = (blockIdx.x & 127) * 4;
    const int baseRow = b * 512 + n0;

    // Load qh / qe, transposing to h-fastest layouts for pair loads
    for (int idx = tid; idx < 1024; idx += 256) {
        int n = idx >> 8, r = idx & 255, h = r >> 5, o = r & 31;
        qhp[(n * 32 + o) * 8 + h] = g_qh[baseRow * 256 + idx];
    }
    for (int idx = tid; idx < 2048; idx += 256) {
        int n = idx >> 9, r = idx & 511, h = r >> 6, j = r & 63;
        qep[(n * 64 + j) * 8 + h] = g_qe[baseRow * 512 + idx];
    }
    __syncthreads();

    // ---- Phase B: logits[n][h][m] = edge-dot + qk-dot, packed over h-pairs ----
    const float* kkb = g_kk + (size_t)b * 512 * 256;
    for (int m = tid; m < 512; m += 256) {
        u64 acc[4][4];
#pragma unroll
        for (int n = 0; n < 4; n++)
#pragma unroll
            for (int p = 0; p < 4; p++) acc[n][p] = 0ull;

        // edge part: acc[n][h-pair] += e[n][j] * qe[n][j][h-pair]
#pragma unroll
        for (int n = 0; n < 4; n++) {
            const float4* ep = (const float4*)(edge +
                ((size_t)(baseRow + n) * 512 + m) * 64);
#pragma unroll 4
            for (int j4 = 0; j4 < 16; j4++) {
                float4 e = ep[j4];
                float ev[4] = {e.x, e.y, e.z, e.w};
#pragma unroll
                for (int s = 0; s < 4; s++) {
                    u64 eb = bcast2(ev[s]);
                    const ulonglong2* qp =
                        (const ulonglong2*)&qep[(n * 64 + j4 * 4 + s) * 8];
                    ulonglong2 qa = qp[0];
                    ulonglong2 qb = qp[1];
                    fma2(acc[n][0], eb, qa.x);
                    fma2(acc[n][1], eb, qa.y);
                    fma2(acc[n][2], eb, qb.x);
                    fma2(acc[n][3], eb, qb.y);
                }
            }
        }

        // qk part: acc[n][h-pair] += kk[m][o][h-pair] * qh[n][o][h-pair]
        const ulonglong2* kp = (const ulonglong2*)(kkb + (size_t)m * 256);
#pragma unroll 4
        for (int o = 0; o < 32; o++) {
            ulonglong2 k01 = kp[o * 2];
            ulonglong2 k23 = kp[o * 2 + 1];
#pragma unroll
            for (int n = 0; n < 4; n++) {
                const ulonglong2* qp = (const ulonglong2*)&qhp[(n * 32 + o) * 8];
                ulonglong2 qa = qp[0];
                ulonglong2 qb = qp[1];
                fma2(acc[n][0], k01.x, qa.x);
                fma2(acc[n][1], k01.y, qa.y);
                fma2(acc[n][2], k23.x, qb.x);
                fma2(acc[n][3], k23.y, qb.y);
            }
        }

#pragma unroll
        for (int n = 0; n < 4; n++)
#pragma unroll
            for (int p = 0; p < 4; p++) {
                float2 f = unpack2(acc[n][p]);
                Ls[(n * 8 + p * 2    ) * 512 + m] = f.x;
                Ls[(n * 8 + p * 2 + 1) * 512 + m] = f.y;
            }
    }
    __syncthreads();

    // ---- Phase C: softmax over m for each of 32 (n,h) rows ----
    {
        const int warp = tid >> 5, lane = tid & 31;
        for (int row = warp; row < 32; row += 8) {
            float* L = Ls + row * 512;
            float mx = -1e30f;
#pragma unroll
            for (int k = 0; k < 16; k++) mx = fmaxf(mx, L[lane + k * 32]);
#pragma unroll
            for (int s = 16; s > 0; s >>= 1)
                mx = fmaxf(mx, __shfl_xor_sync(0xffffffff, mx, s));
            float sum = 0.f;
#pragma unroll
            for (int k = 0; k < 16; k++) {
                float p = __expf(L[lane + k * 32] - mx);
                L[lane + k * 32] = p;
                sum += p;
            }
#pragma unroll
            for (int s = 16; s > 0; s >>= 1)
                sum += __shfl_xor_sync(0xffffffff, sum, s);
            if (lane == 0) rsum[row] = sum;
        }
    }
    __syncthreads();

    // ---- Phase D: mh[n][c] = sum_m p[n][h][m] * vT[m][c], f32x2 over m-pairs ----
    {
        const int c = tid, h = tid >> 5;
        const ulonglong2* vp = (const ulonglong2*)g_vT + (size_t)b * 32768 + c;
        u64 acc2[4] = {0ull, 0ull, 0ull, 0ull};
#pragma unroll 4
        for (int mq = 0; mq < 128; mq++) {
            ulonglong2 vv = vp[mq * 256];       // v[4m][c], coalesced
#pragma unroll
            for (int n = 0; n < 4; n++) {
                ulonglong2 pp = *(const ulonglong2*)&Ls[(n * 8 + h) * 512 + mq * 4];
                fma2(acc2[n], vv.x, pp.x);
                fma2(acc2[n], vv.y, pp.y);
            }
        }
#pragma unroll
        for (int n = 0; n < 4; n++) {
            float2 f = unpack2(acc2[n]);
            mh_s[n * 256 + c] = (f.x + f.y) / rsum[n * 8 + h];
        }
    }
    __syncthreads();

    // ---- Phase E: out[n][c] = mh[n] . P[:,:,c] + bias[c] ----
    {
        const int c = tid & 127;
        const int g = tid >> 7;
        float a0 = bias[c], a1 = bias[c];
#pragma unroll 4
        for (int ho = 0; ho < 256; ho++) {
            float p = P[ho * 128 + c];
            a0 += mh_s[g * 256 + ho] * p;
            a1 += mh_s[(g + 2) * 256 + ho] * p;
        }
        out[(size_t)(baseRow + g) * 128 + c] = a0;
        out[(size_t)(baseRow + g + 2) * 128 + c] = a1;
    }
}

// ---------------------------------------------------------------------------
extern "C" void kernel_launch(void* const* d_in, const int* in_sizes, int n_in,
                              void* d_out, int out_size) {
    const float* query = (const float*)d_in[0];
    const float* key   = (const float*)d_in[1];
    const float* value = (const float*)d_in[2];
    const float* edge  = (const float*)d_in[3];
    const float* Wq    = (const float*)d_in[4];
    const float* Wk    = (const float*)d_in[5];
    const float* Wv    = (const float*)d_in[6];
    const float* P     = (const float*)d_in[7];
    const float* bias  = (const float*)d_in[8];
    float* out = (float*)d_out;

    cudaFuncSetAttribute(attn_kernel,
                         cudaFuncAttributeMaxDynamicSharedMemorySize, SMEM_BYTES);

    prologue_kernel<<<512, 256>>>(query, key, value, Wq, Wk, Wv);
    attn_kernel<<<256, 256, SMEM_BYTES>>>(edge, P, bias, out);
}

// round 14
// speedup vs baseline: 1.4698x; 1.4698x over previous
#include <cuda_runtime.h>

// Shapes (fixed): B=2, N=512, M=512, Dq=Dk=Dv=128, De=64, H=8, O=32, OUT=128

#define BB 2
#define NN 512
#define MM 512
#define HH 8
#define OO 32
#define DE 64

typedef unsigned long long u64;

// Scratch (no cudaMalloc allowed). ~4.5 MB total.
__device__ __align__(256) float g_qh[BB*NN*HH*OO];   // [row][h*32+o]
__device__ __align__(256) float g_qe[BB*NN*HH*DE];   // [row][h*64+j]
__device__ __align__(256) float g_kk[BB*OO*4*MM*2];  // [b][o][hp][m][2h]  (u64 per (o,hp,m))
__device__ __align__(256) float g_vT[BB*512*256];    // [b][m/4][c][4]  c=h*32+o

// ---------------------------------------------------------------------------
// Packed fp32x2 helpers (FFMA2 via PTX fma.rn.f32x2)
// ---------------------------------------------------------------------------
__device__ __forceinline__ void fma2(u64 &d, u64 a, u64 b) {
    asm("fma.rn.f32x2 %0, %1, %2, %0;" : "+l"(d) : "l"(a), "l"(b));
}
__device__ __forceinline__ u64 bcast2(float x) {
    u64 r; asm("mov.b64 %0, {%1, %1};" : "=l"(r) : "f"(x)); return r;
}
__device__ __forceinline__ float2 unpack2(u64 v) {
    float2 f; asm("mov.b64 {%0, %1}, %2;" : "=f"(f.x), "=f"(f.y) : "l"(v)); return f;
}

// ---------------------------------------------------------------------------
// Fused prologue: 512 blocks x 256 threads.
//   type = id&1 (0: q-side, 1: kv-side), h = (id>>1)&7, chunk = id>>4
// ---------------------------------------------------------------------------
__global__ __launch_bounds__(256) void prologue_kernel(
    const float* __restrict__ query,
    const float* __restrict__ key,
    const float* __restrict__ value,
    const float* __restrict__ Wq,   // [H,128,32]
    const float* __restrict__ Wk,   // [H,192,32]
    const float* __restrict__ Wv)   // [H,128,32]
{
    __shared__ float sm[16384];
    const int tid = threadIdx.x;
    const int id = blockIdx.x;
    const int type = id & 1;
    const int h = (id >> 1) & 7;
    const int chunk = id >> 4;      // 0..31
    const int r0 = chunk * 32;      // global row base (0..1023)

    if (type == 0) {
        float* q_s  = sm;           // [32][128]
        float* Wq_s = sm + 4096;    // [128][32]
        float* We_s = sm + 8192;    // [o][j] = [32][64]
        float* qh_s = sm + 10240;   // [32][32]

        for (int i = tid; i < 4096; i += 256) {
            q_s[i]  = query[r0 * 128 + i];
            Wq_s[i] = Wq[h * 4096 + i];
        }
        for (int i = tid; i < 2048; i += 256) {
            int j = i >> 5, o = i & 31;
            We_s[o * 64 + j] = Wk[h * 6144 + 4096 + i];   // Wk[h][128+j][o]
        }
        __syncthreads();

        {   // qh = q @ Wq_h, scaled
            const int o = tid & 31, rg = tid >> 5;
            float acc[4] = {0.f, 0.f, 0.f, 0.f};
#pragma unroll 4
            for (int i = 0; i < 128; i++) {
                float w = Wq_s[i * 32 + o];
#pragma unroll
                for (int c = 0; c < 4; c++) acc[c] += q_s[(rg * 4 + c) * 128 + i] * w;
            }
            const float scale = 0.17677669529663687f;     // 1/sqrt(32)
#pragma unroll
            for (int c = 0; c < 4; c++) {
                int r = rg * 4 + c;
                float v = acc[c] * scale;
                qh_s[r * 32 + o] = v;
                g_qh[(r0 + r) * 256 + h * 32 + o] = v;
            }
        }
        __syncthreads();

        {   // qe[h][j] = sum_o qh[h][o] * We[j][o]
            const int j = tid & 63, rg = tid >> 6;
            float acc[8] = {0.f,0.f,0.f,0.f,0.f,0.f,0.f,0.f};
#pragma unroll 4
            for (int o = 0; o < 32; o++) {
                float w = We_s[o * 64 + j];
#pragma unroll
                for (int c = 0; c < 8; c++) acc[c] += qh_s[(rg * 8 + c) * 32 + o] * w;
            }
#pragma unroll
            for (int c = 0; c < 8; c++)
                g_qe[(r0 + rg * 8 + c) * 512 + h * 64 + j] = acc[c];
        }
    } else {
        float* k_s  = sm;
        float* v_s  = sm + 4096;
        float* Wk_s = sm + 8192;
        float* Wv_s = sm + 12288;

        for (int i = tid; i < 4096; i += 256) {
            k_s[i]  = key[r0 * 128 + i];
            v_s[i]  = value[r0 * 128 + i];
            Wk_s[i] = Wk[h * 6144 + i];
            Wv_s[i] = Wv[h * 4096 + i];
        }
        __syncthreads();

        const int o = tid & 31, rg = tid >> 5;
        float ak[4] = {0.f,0.f,0.f,0.f}, av[4] = {0.f,0.f,0.f,0.f};
#pragma unroll 4
        for (int i = 0; i < 128; i++) {
            float wk = Wk_s[i * 32 + o];
            float wv = Wv_s[i * 32 + o];
#pragma unroll
            for (int c = 0; c < 4; c++) {
                ak[c] += k_s[(rg * 4 + c) * 128 + i] * wk;
                av[c] += v_s[(rg * 4 + c) * 128 + i] * wv;
            }
        }
        // g_kk layout: [b][o][hp][m][2]
#pragma unroll
        for (int c = 0; c < 4; c++) {
            int r = r0 + rg * 4 + c;
            int b = r >> 9, m = r & 511;
            g_kk[((((size_t)b * 32 + o) * 4 + (h >> 1)) * 512 + m) * 2 + (h & 1)] = ak[c];
        }

        // transpose av through smem (padded) then write g_vT coalesced
        __syncthreads();
        float* vt = sm;                  // [32 o][33] padded
#pragma unroll
        for (int c = 0; c < 4; c++)
            vt[o * 33 + rg * 4 + c] = av[c];
        __syncthreads();

        {
            const int o2 = tid >> 3, r4 = tid & 7;
            float4 val;
            val.x = vt[o2 * 33 + r4 * 4 + 0];
            val.y = vt[o2 * 33 + r4 * 4 + 1];
            val.z = vt[o2 * 33 + r4 * 4 + 2];
            val.w = vt[o2 * 33 + r4 * 4 + 3];
            const int b = r0 >> 9, mm0 = r0 & 511;
            size_t fidx = ((size_t)(b * 128 + (mm0 >> 2) + r4) * 256 + (h * 32 + o2)) * 4;
            *(float4*)&g_vT[fidx] = val;
        }
    }
}

// ---------------------------------------------------------------------------
// Main fused kernel: block = (b, 4 n-rows). 256 threads.
// Smem (floats):
//   Ls     [32][512]              @0      (16384)
//   edge_s [4n][64j][32m] swizzled@16384  (8192)
//   qep    [n][j][8h]             @24576  (2048)
//   qhp    [n][o][8h]             @26624  (1024)
//   mh_s   [4][256]               @27648  (1024)
//   rsum   [32]                   @28672  (32)
// total 28704 floats = 114816 B  -> 2 blocks/SM
// ---------------------------------------------------------------------------
#define SMEM_BYTES (28704 * 4)

__global__ __launch_bounds__(256, 2) void attn_kernel(
    const float* __restrict__ edge,   // [B,N,M,64]
    const float* __restrict__ P,      // [H,32,128]
    const float* __restrict__ bias,   // [128]
    float* __restrict__ out)          // [B,N,128]
{
    extern __shared__ float smem[];
    float* Ls     = smem;
    float* edge_s = smem + 16384;
    float* qep    = smem + 24576;
    float* qhp    = smem + 26624;
    float* mh_s   = smem + 27648;
    float* rsum   = smem + 28672;

    const int tid = threadIdx.x;
    const int b  = blockIdx.x >> 7;
    const int n0 = (blockIdx.x & 127) * 4;
    const int baseRow = b * 512 + n0;

    // Load qh / qe into h-fastest layouts
    for (int idx = tid; idx < 1024; idx += 256) {
        int n = idx >> 8, r = idx & 255, h = r >> 5, o = r & 31;
        qhp[(n * 32 + o) * 8 + h] = g_qh[baseRow * 256 + idx];
    }
    for (int idx = tid; idx < 2048; idx += 256) {
        int n = idx >> 9, r = idx & 511, h = r >> 6, j = r & 63;
        qep[(n * 64 + j) * 8 + h] = g_qe[baseRow * 512 + idx];
    }
    __syncthreads();

    // ---- Phase B: logits over m-tiles of 32, edge staged in smem ----
    const int warp = tid >> 5, lane = tid & 31;
    const int wn = warp >> 1, hq = warp & 1;     // warp handles (n=wn, h quad hq)
    const u64* kkb = (const u64*)g_kk + ((size_t)b * 32 * 4 * 512) + (size_t)(hq * 2) * 512;

    // staging decode (loop-invariant)
    const int sn  = tid >> 9;                    // always 0 for k-base; recompute per k
    (void)sn;

    for (int tile = 0; tile < 16; tile++) {
        const int m0 = tile * 32;

        // stage edge[4n][32m][64j] -> edge_s[n][j][(m+j)&31], coalesced reads
#pragma unroll
        for (int k = 0; k < 8; k++) {
            int idx = tid + k * 256;             // 0..2047 float4 units
            int n = idx >> 9, m = (idx >> 4) & 31, j4 = idx & 15;
            float4 e = ((const float4*)(edge +
                ((size_t)(baseRow + n) * 512 + m0 + m) * 64))[j4];
            float ev[4] = {e.x, e.y, e.z, e.w};
#pragma unroll
            for (int q = 0; q < 4; q++) {
                int j = j4 * 4 + q;
                edge_s[(n * 64 + j) * 32 + ((m + j) & 31)] = ev[q];
            }
        }
        __syncthreads();

        // compute: lane owns m = m0 + lane; warp owns (wn, 4 h's of quad hq)
        u64 acc0 = 0ull, acc1 = 0ull;

        // edge part
#pragma unroll 8
        for (int j = 0; j < 64; j++) {
            float e = edge_s[(wn * 64 + j) * 32 + ((lane + j) & 31)];
            u64 eb = bcast2(e);
            ulonglong2 q2 = *(const ulonglong2*)&qep[(wn * 64 + j) * 8 + hq * 4];
            fma2(acc0, eb, q2.x);
            fma2(acc1, eb, q2.y);
        }

        // qk part: kk[b][o][hp][m] u64, coalesced over lane-m
        const int m = m0 + lane;
#pragma unroll 8
        for (int o = 0; o < 32; o++) {
            u64 k0 = kkb[(size_t)o * 2048 + m];
            u64 k1 = kkb[(size_t)o * 2048 + 512 + m];
            ulonglong2 q2 = *(const ulonglong2*)&qhp[(wn * 32 + o) * 8 + hq * 4];
            fma2(acc0, k0, q2.x);
            fma2(acc1, k1, q2.y);
        }

        float2 f0 = unpack2(acc0);
        float2 f1 = unpack2(acc1);
        Ls[(wn * 8 + hq * 4 + 0) * 512 + m] = f0.x;
        Ls[(wn * 8 + hq * 4 + 1) * 512 + m] = f0.y;
        Ls[(wn * 8 + hq * 4 + 2) * 512 + m] = f1.x;
        Ls[(wn * 8 + hq * 4 + 3) * 512 + m] = f1.y;
        __syncthreads();   // edge_s reused next tile
    }

    // ---- Phase C: softmax over m for each of 32 (n,h) rows ----
    {
        for (int row = warp; row < 32; row += 8) {
            float* L = Ls + row * 512;
            float mx = -1e30f;
#pragma unroll
            for (int k = 0; k < 16; k++) mx = fmaxf(mx, L[lane + k * 32]);
#pragma unroll
            for (int s = 16; s > 0; s >>= 1)
                mx = fmaxf(mx, __shfl_xor_sync(0xffffffff, mx, s));
            float sum = 0.f;
#pragma unroll
            for (int k = 0; k < 16; k++) {
                float p = __expf(L[lane + k * 32] - mx);
                L[lane + k * 32] = p;
                sum += p;
            }
#pragma unroll
            for (int s = 16; s > 0; s >>= 1)
                sum += __shfl_xor_sync(0xffffffff, sum, s);
            if (lane == 0) rsum[row] = sum;
        }
    }
    __syncthreads();

    // ---- Phase D: mh[n][c] = sum_m p[n][h][m] * vT[m][c], f32x2 over m-pairs ----
    {
        const int c = tid, h = tid >> 5;
        const ulonglong2* vp = (const ulonglong2*)g_vT + (size_t)b * 32768 + c;
        u64 acc2[4] = {0ull, 0ull, 0ull, 0ull};
#pragma unroll 4
        for (int mq = 0; mq < 128; mq++) {
            ulonglong2 vv = vp[mq * 256];       // v[4m][c], coalesced
#pragma unroll
            for (int n = 0; n < 4; n++) {
                ulonglong2 pp = *(const ulonglong2*)&Ls[(n * 8 + h) * 512 + mq * 4];
                fma2(acc2[n], vv.x, pp.x);
                fma2(acc2[n], vv.y, pp.y);
            }
        }
#pragma unroll
        for (int n = 0; n < 4; n++) {
            float2 f = unpack2(acc2[n]);
            mh_s[n * 256 + c] = (f.x + f.y) / rsum[n * 8 + h];
        }
    }
    __syncthreads();

    // ---- Phase E: out[n][c] = mh[n] . P[:,:,c] + bias[c] ----
    {
        const int c = tid & 127;
        const int g = tid >> 7;
        float a0 = bias[c], a1 = bias[c];
#pragma unroll 4
        for (int ho = 0; ho < 256; ho++) {
            float p = P[ho * 128 + c];
            a0 += mh_s[g * 256 + ho] * p;
            a1 += mh_s[(g + 2) * 256 + ho] * p;
        }
        out[(size_t)(baseRow + g) * 128 + c] = a0;
        out[(size_t)(baseRow + g + 2) * 128 + c] = a1;
    }
}

// ---------------------------------------------------------------------------
extern "C" void kernel_launch(void* const* d_in, const int* in_sizes, int n_in,
                              void* d_out, int out_size) {
    const float* query = (const float*)d_in[0];
    const float* key   = (const float*)d_in[1];
    const float* value = (const float*)d_in[2];
    const float* edge  = (const float*)d_in[3];
    const float* Wq    = (const float*)d_in[4];
    const float* Wk    = (const float*)d_in[5];
    const float* Wv    = (const float*)d_in[6];
    const float* P     = (const float*)d_in[7];
    const float* bias  = (const float*)d_in[8];
    float* out = (float*)d_out;

    cudaFuncSetAttribute(attn_kernel,
                         cudaFuncAttributeMaxDynamicSharedMemorySize, SMEM_BYTES);

    prologue_kernel<<<512, 256>>>(query, key, value, Wq, Wk, Wv);
    attn_kernel<<<256, 256, SMEM_BYTES>>>(edge, P, bias, out);
}